// round 17
// baseline (speedup 1.0000x reference)
#include <cuda_runtime.h>
#include <cuda_bf16.h>
#include <stdint.h>
#include <math.h>

// ---------------------------------------------------------------------------
// Problem constants
// ---------------------------------------------------------------------------
#define BATCH   2
#define LSEQ    2048
#define DIMC    256
#define DI      512          // d_inner
#define DS      64           // d_state
#define DTR     16           // dt_rank
#define XDBLW   144          // dt_rank + 2*d_state
#define NTOK    (BATCH*LSEQ) // 4096
#define SQRT_INV_8192 0.011048543456039806f
#define LAMBDA_SS 0.01f
#define PI_F 3.14159265358979323846f

// weight sizes (elems)
#define W_IN_SZ (2*DI*DIMC)   // 262144
#define W_X_SZ  (XDBLW*DI)    // 73728
#define W_O_SZ  (DIMC*DI)     // 131072

// ---------------------------------------------------------------------------
// Scratch (single __device__ array; no allocations anywhere)
// ---------------------------------------------------------------------------
#define O_XDBL  ((size_t)0)                                // fp32 NTOK*XDBLW
#define O_X1    (O_XDBL + (size_t)NTOK*XDBLW)              // fp32 NTOK*DIMC
#define O_XZB   (O_X1   + (size_t)NTOK*DIMC)               // bf16 NTOK*2*DI
#define O_XNBF  (O_XZB  + (size_t)NTOK*DI)                 // bf16 NTOK*DIMC
#define O_XCBF  (O_XNBF + (size_t)NTOK*DIMC/2)             // bf16 NTOK*DI
#define O_YBF   (O_XCBF + (size_t)NTOK*DI/2)               // bf16 NTOK*DI
#define O_XN2B  (O_YBF  + (size_t)NTOK*DI/2)               // bf16 NTOK*DIMC
#define O_FRB   (O_XN2B + (size_t)NTOK*DIMC/2)             // bf16 NTOK*DIMC
#define O_FIB   (O_FRB  + (size_t)NTOK*DIMC/2)             // bf16 NTOK*DIMC
#define O_WBF   (O_FIB  + (size_t)NTOK*DIMC/2)             // bf16 weights
#define O_END   (O_WBF  + (size_t)(W_IN_SZ+W_X_SZ+W_O_SZ)/2 + 64)

__device__ float SCRATCH[O_END];

// ---------------------------------------------------------------------------
// cp.async + f32x2 helpers
// ---------------------------------------------------------------------------
__device__ __forceinline__ void cp16(unsigned dst, const void* src, int sz) {
    asm volatile("cp.async.cg.shared.global [%0], [%1], 16, %2;"
                 :: "r"(dst), "l"(src), "r"(sz));
}
__device__ __forceinline__ void cp_commit() {
    asm volatile("cp.async.commit_group;" ::: "memory");
}
template <int N>
__device__ __forceinline__ void cp_wait() {
    asm volatile("cp.async.wait_group %0;" :: "n"(N) : "memory");
}

typedef unsigned long long u64;
__device__ __forceinline__ u64 packf2(float lo, float hi) {
    u64 r;
    asm("mov.b64 %0, {%1, %2};" : "=l"(r) : "f"(lo), "f"(hi));
    return r;
}
__device__ __forceinline__ void unpackf2(u64 v, float& lo, float& hi) {
    asm("mov.b64 {%0, %1}, %2;" : "=f"(lo), "=f"(hi) : "l"(v));
}
__device__ __forceinline__ void fma2(u64& d, u64 a, u64 b, u64 c) {
    asm("fma.rn.f32x2 %0, %1, %2, %3;" : "=l"(d) : "l"(a), "l"(b), "l"(c));
}
// 11-bit bit reversal (positions 0..2047)
__device__ __forceinline__ int rev11(int p) {
    return (int)(__brev((unsigned)p) >> 21);
}

// ---------------------------------------------------------------------------
// LayerNorm body (one warp per token); writes fp32 and/or bf16.
// ---------------------------------------------------------------------------
__device__ __forceinline__ void ln_body(int t, int lane,
                                        const float* __restrict__ x,
                                        const float* __restrict__ w,
                                        const float* __restrict__ b,
                                        float* __restrict__ out,
                                        __nv_bfloat16* __restrict__ obf) {
    const float4* row = (const float4*)(x + (size_t)t * DIMC);
    float4 v0 = row[lane];
    float4 v1 = row[lane + 32];
    float s = v0.x + v0.y + v0.z + v0.w + v1.x + v1.y + v1.z + v1.w;
    #pragma unroll
    for (int off = 16; off; off >>= 1) s += __shfl_xor_sync(0xffffffffu, s, off);
    float m = s * (1.0f / 256.0f);
    float d0 = v0.x - m, d1 = v0.y - m, d2 = v0.z - m, d3 = v0.w - m;
    float d4 = v1.x - m, d5 = v1.y - m, d6 = v1.z - m, d7 = v1.w - m;
    float q = d0*d0 + d1*d1 + d2*d2 + d3*d3 + d4*d4 + d5*d5 + d6*d6 + d7*d7;
    #pragma unroll
    for (int off = 16; off; off >>= 1) q += __shfl_xor_sync(0xffffffffu, q, off);
    float inv = rsqrtf(q * (1.0f / 256.0f) + 1e-5f);
    const float4* w4 = (const float4*)w;
    const float4* b4 = (const float4*)b;
    float4 wa = w4[lane], ba = b4[lane];
    float4 wb = w4[lane + 32], bb = b4[lane + 32];
    float4 r0, r1;
    r0.x = d0*inv*wa.x + ba.x; r0.y = d1*inv*wa.y + ba.y;
    r0.z = d2*inv*wa.z + ba.z; r0.w = d3*inv*wa.w + ba.w;
    r1.x = d4*inv*wb.x + bb.x; r1.y = d5*inv*wb.y + bb.y;
    r1.z = d6*inv*wb.z + bb.z; r1.w = d7*inv*wb.w + bb.w;
    if (out) {
        float4* o4 = (float4*)(out + (size_t)t * DIMC);
        o4[lane] = r0; o4[lane + 32] = r1;
    }
    if (obf) {
        __nv_bfloat162* o2 = (__nv_bfloat162*)(obf + (size_t)t * DIMC);
        o2[lane*2]      = __nv_bfloat162(__float2bfloat16_rn(r0.x), __float2bfloat16_rn(r0.y));
        o2[lane*2 + 1]  = __nv_bfloat162(__float2bfloat16_rn(r0.z), __float2bfloat16_rn(r0.w));
        o2[64 + lane*2]     = __nv_bfloat162(__float2bfloat16_rn(r1.x), __float2bfloat16_rn(r1.y));
        o2[64 + lane*2 + 1] = __nv_bfloat162(__float2bfloat16_rn(r1.z), __float2bfloat16_rn(r1.w));
    }
}

// ---------------------------------------------------------------------------
// Prep: weight fp32->bf16 convert (blocks 0..295) + LN1 (blocks 296..807).
// ---------------------------------------------------------------------------
#define WCVT_BLOCKS 296
__global__ void prep_kernel(const float* __restrict__ w_in,
                            const float* __restrict__ w_x,
                            const float* __restrict__ w_o,
                            __nv_bfloat16* __restrict__ wdst,
                            const float* __restrict__ x,
                            const float* __restrict__ n1w,
                            const float* __restrict__ n1b,
                            __nv_bfloat16* __restrict__ xnbf) {
    if (blockIdx.x < WCVT_BLOCKS) {
        int total = W_IN_SZ + W_X_SZ + W_O_SZ;
        for (int i = blockIdx.x * 256 + threadIdx.x; i < total;
             i += WCVT_BLOCKS * 256) {
            float v;
            if (i < W_IN_SZ) v = w_in[i];
            else if (i < W_IN_SZ + W_X_SZ) v = w_x[i - W_IN_SZ];
            else v = w_o[i - W_IN_SZ - W_X_SZ];
            wdst[i] = __float2bfloat16_rn(v);
        }
    } else {
        int t = (blockIdx.x - WCVT_BLOCKS) * 8 + (threadIdx.x >> 5);
        ln_body(t, threadIdx.x & 31, x, n1w, n1b, nullptr, xnbf);
    }
}

// LN2 standalone
__global__ void ln_kernel(const float* __restrict__ x,
                          const float* __restrict__ w,
                          const float* __restrict__ b,
                          float* __restrict__ out,
                          __nv_bfloat16* __restrict__ obf) {
    ln_body(blockIdx.x * 8 + (threadIdx.x >> 5), threadIdx.x & 31,
            x, w, b, out, obf);
}

// ---------------------------------------------------------------------------
// bf16 tensor-core GEMM: out = A[M,K] * W[N,K]^T (+ R).  Output fp32 or bf16.
// ---------------------------------------------------------------------------
#define GBM 128
#define GBN 64
#define BK  32
#define HSTR 40
#define GSTAGES 4
#define GEMM_SMEM (GSTAGES * (GBM + GBN) * HSTR * 2)

__device__ __forceinline__ void mma_bf16(float* c, const unsigned* a, const unsigned* b) {
    asm volatile(
        "mma.sync.aligned.m16n8k16.row.col.f32.bf16.bf16.f32 "
        "{%0,%1,%2,%3}, {%4,%5,%6,%7}, {%8,%9}, {%0,%1,%2,%3};"
        : "+f"(c[0]), "+f"(c[1]), "+f"(c[2]), "+f"(c[3])
        : "r"(a[0]), "r"(a[1]), "r"(a[2]), "r"(a[3]), "r"(b[0]), "r"(b[1]));
}

__global__ void __launch_bounds__(256) gemm_bf16(const __nv_bfloat16* __restrict__ A,
                                                 const __nv_bfloat16* __restrict__ W,
                                                 const float* __restrict__ R,
                                                 float* __restrict__ C,
                                                 __nv_bfloat16* __restrict__ Cbf,
                                                 int M, int N, int K) {
    extern __shared__ __nv_bfloat16 hsm[];
    __nv_bfloat16* As = hsm;
    __nv_bfloat16* Bs = hsm + GSTAGES * GBM * HSTR;
    unsigned smA = (unsigned)__cvta_generic_to_shared(As);
    unsigned smB = (unsigned)__cvta_generic_to_shared(Bs);

    int m0 = blockIdx.y * GBM;
    int n0 = blockIdx.x * GBN;
    int tid = threadIdx.x;
    int wid = tid >> 5, lane = tid & 31;
    int wm = (wid & 3) * 32;
    int wn = (wid >> 2) * 32;
    int gid = lane >> 2;
    int tig = lane & 3;
    int ar = tid >> 1, akq = (tid & 1) * 16;
    int br = tid >> 2, bkq = (tid & 3) * 8;

    const __nv_bfloat16* Abase = A + (size_t)(m0 + ar) * K + akq;
    bool bok = (n0 + br) < N;
    const __nv_bfloat16* Bbase = bok ? (W + (size_t)(n0 + br) * K + bkq) : W;
    int bsz = bok ? 16 : 0;
    unsigned adst = smA + (unsigned)(ar * HSTR + akq) * 2u;
    unsigned bdst = smB + (unsigned)(br * HSTR + bkq) * 2u;
    const unsigned aStage = GBM * HSTR * 2u;
    const unsigned bStage = GBN * HSTR * 2u;

    float acc[2][4][4];
    #pragma unroll
    for (int mi = 0; mi < 2; mi++)
        #pragma unroll
        for (int ni = 0; ni < 4; ni++)
            #pragma unroll
            for (int q = 0; q < 4; q++) acc[mi][ni][q] = 0.0f;

    int nIt = K / BK;
    #pragma unroll
    for (int s = 0; s < GSTAGES - 1; s++) {
        cp16(adst + s * aStage,      Abase + s * BK,     16);
        cp16(adst + s * aStage + 16, Abase + s * BK + 8, 16);
        cp16(bdst + s * bStage,      Bbase + (bok ? s * BK : 0), bsz);
        cp_commit();
    }

    for (int it = 0; it < nIt; it++) {
        cp_wait<GSTAGES - 2>();
        __syncthreads();
        int buf = it & (GSTAGES - 1);
        const __nv_bfloat16* Ab = As + buf * (GBM * HSTR);
        const __nv_bfloat16* Bb = Bs + buf * (GBN * HSTR);
        #pragma unroll
        for (int ks = 0; ks < 2; ks++) {
            int k16 = ks * 16;
            unsigned afr[2][4], bfr[4][2];
            #pragma unroll
            for (int mi = 0; mi < 2; mi++) {
                int rb = wm + mi * 16 + gid;
                afr[mi][0] = *(const unsigned*)(Ab + (rb)     * HSTR + k16 + tig * 2);
                afr[mi][1] = *(const unsigned*)(Ab + (rb + 8) * HSTR + k16 + tig * 2);
                afr[mi][2] = *(const unsigned*)(Ab + (rb)     * HSTR + k16 + tig * 2 + 8);
                afr[mi][3] = *(const unsigned*)(Ab + (rb + 8) * HSTR + k16 + tig * 2 + 8);
            }
            #pragma unroll
            for (int ni = 0; ni < 4; ni++) {
                int cb = wn + ni * 8 + gid;
                bfr[ni][0] = *(const unsigned*)(Bb + cb * HSTR + k16 + tig * 2);
                bfr[ni][1] = *(const unsigned*)(Bb + cb * HSTR + k16 + tig * 2 + 8);
            }
            #pragma unroll
            for (int mi = 0; mi < 2; mi++)
                #pragma unroll
                for (int ni = 0; ni < 4; ni++)
                    mma_bf16(acc[mi][ni], afr[mi], bfr[ni]);
        }
        int nx = it + GSTAGES - 1;
        if (nx < nIt) {
            int slot = nx & (GSTAGES - 1);
            cp16(adst + slot * aStage,      Abase + nx * BK,     16);
            cp16(adst + slot * aStage + 16, Abase + nx * BK + 8, 16);
            cp16(bdst + slot * bStage,      Bbase + (bok ? nx * BK : 0), bsz);
        }
        cp_commit();
    }

    #pragma unroll
    for (int mi = 0; mi < 2; mi++) {
        int row = m0 + wm + mi * 16 + gid;
        #pragma unroll
        for (int ni = 0; ni < 4; ni++) {
            int col = n0 + wn + ni * 8 + tig * 2;
            #pragma unroll
            for (int half = 0; half < 2; half++) {
                int rr = row + half * 8;
                float v0 = acc[mi][ni][half * 2];
                float v1 = acc[mi][ni][half * 2 + 1];
                if (col < N) {
                    if (Cbf) Cbf[(size_t)rr * N + col] = __float2bfloat16_rn(v0);
                    else {
                        if (R) v0 += R[(size_t)rr * N + col];
                        C[(size_t)rr * N + col] = v0;
                    }
                }
                if (col + 1 < N) {
                    if (Cbf) Cbf[(size_t)rr * N + col + 1] = __float2bfloat16_rn(v1);
                    else {
                        if (R) v1 += R[(size_t)rr * N + col + 1];
                        C[(size_t)rr * N + col + 1] = v1;
                    }
                }
            }
        }
    }
}

// ---------------------------------------------------------------------------
// Depthwise causal conv (k=4) + bias + SiLU, bf16 in -> bf16 out only.
// ---------------------------------------------------------------------------
__global__ void conv_silu_kernel(const __nv_bfloat16* __restrict__ xzb,
                                 const float* __restrict__ cw,
                                 const float* __restrict__ cb,
                                 __nv_bfloat16* __restrict__ xc_bf) {
    int idx = blockIdx.x * 256 + threadIdx.x;
    int d = idx & (DI - 1);
    int bt = idx >> 9;
    int b = bt >> 11;
    int l = bt & (LSEQ - 1);
    float acc = cb[d];
    #pragma unroll
    for (int k = 0; k < 4; k++) {
        int ls = l + k - 3;
        if (ls >= 0)
            acc += __bfloat162float(xzb[((size_t)((b << 11) | ls)) * (2 * DI) + d])
                   * cw[d * 4 + k];
    }
    float v = acc / (1.0f + __expf(-acc));
    xc_bf[(size_t)bt * DI + d] = __float2bfloat16_rn(v);
}

// ---------------------------------------------------------------------------
// Selective scan: fused dt, deferred reduce-scatter, cp.async double-buffered.
// MUFU reduction: when A has the reference structure (A1 = A0 + A0@lane31,
// exactly the case for A = -arange(1..64)), dA1 = dA0 * shfl(dA0, 31) -- one
// exp per step instead of two.  Runtime-checked with exact-exp fallback.
// ---------------------------------------------------------------------------
#define TCHUNK 64
#define SXW 148
#define SCAN_F (2*64*SXW + 512 + 512 + 128 + 8)
#define SCAN_SMEM (SCAN_F * 4 + 2 * (2*64*8*2))

__global__ void __launch_bounds__(256) scan_kernel(
        const float* __restrict__ xdbl,
        const __nv_bfloat16* __restrict__ xcb,
        const __nv_bfloat16* __restrict__ xzb,
        const float* __restrict__ A_log,
        const float* __restrict__ Dvec,
        const float* __restrict__ dtw,
        const float* __restrict__ dtb,
        __nv_bfloat16* __restrict__ y_bf) {
    extern __shared__ float ssm[];
    float* sX   = ssm;                      // [2][64][SXW]
    float* sdt  = sX + 2 * 64 * SXW;        // [64][8]
    float* sy   = sdt + 512;                // [64][8]
    float* sw   = sy + 512;                 // [8][16]
    float* sbias= sw + 128;                 // [8]
    __nv_bfloat16* szb  = (__nv_bfloat16*)(sbias + 8);  // [2][64][8]
    __nv_bfloat16* sxcb = szb + 2 * 64 * 8;             // [2][64][8]
    unsigned aX  = (unsigned)__cvta_generic_to_shared(sX);
    unsigned aZ  = (unsigned)__cvta_generic_to_shared(szb);
    unsigned aXC = (unsigned)__cvta_generic_to_shared(sxcb);

    int b = blockIdx.x >> 6;
    int dbase = (blockIdx.x & 63) * 8;
    int wid = threadIdx.x >> 5;
    int lane = threadIdx.x & 31;
    int d = dbase + wid;
    int tid = threadIdx.x;

    if (tid < 128) {
        int di = tid >> 4, r = tid & 15;
        sw[di * 16 + r] = dtw[(dbase + di) * DTR + r];
        if (r == 0) sbias[di] = dtb[dbase + di];
    }
    float A0 = -__expf(A_log[d * DS + lane]);
    float A1 = -__expf(A_log[d * DS + lane + 32]);
    float Dd = Dvec[d];
    float h0 = 0.0f, h1 = 0.0f;

    // Structure check: A1 == A0 + A0(lane31) for all lanes (exp-additivity).
    float a31 = __shfl_sync(0xffffffffu, A0, 31);
    bool fast = __all_sync(0xffffffffu,
                           fabsf((A1 - A0) - a31) <= 1e-5f * fabsf(a31));

    auto stage = [&](int buf, int t0) {
        size_t rowbase = (size_t)(b * LSEQ + t0);
        for (int i = tid; i < 64 * 36; i += 256) {
            int tt = i / 36, q = i - tt * 36;
            cp16(aX + (unsigned)(((buf * 64 + tt) * SXW) + q * 4) * 4u,
                 xdbl + (rowbase + tt) * XDBLW + q * 4, 16);
        }
        if (tid < 128) {
            int tt = tid & 63;
            if (tid < 64)
                cp16(aXC + (unsigned)((buf * 64 + tt) * 8) * 2u,
                     xcb + (rowbase + tt) * DI + dbase, 16);
            else
                cp16(aZ + (unsigned)((buf * 64 + tt) * 8) * 2u,
                     xzb + (rowbase + tt) * (2 * DI) + DI + dbase, 16);
        }
    };

    stage(0, 0);
    cp_commit();

    for (int c = 0; c < LSEQ / TCHUNK; c++) {
        int buf = c & 1;
        cp_wait<0>();
        __syncthreads();
        if (c + 1 < LSEQ / TCHUNK) stage(buf ^ 1, (c + 1) * TCHUNK);
        cp_commit();

        for (int i = tid; i < 512; i += 256) {
            int tt = i >> 3, di = i & 7;
            const float* xr = sX + (buf * 64 + tt) * SXW;
            float acc = sbias[di];
            #pragma unroll
            for (int r = 0; r < 16; r++) acc = fmaf(xr[r], sw[di * 16 + r], acc);
            sdt[tt * 8 + di] = (acc > 20.0f) ? acc : __logf(1.0f + __expf(acc));
        }
        __syncthreads();

        if (fast) {
            #pragma unroll 1
            for (int g = 0; g < TCHUNK / 32; g++) {
                float part[32];
                #pragma unroll
                for (int j = 0; j < 32; j++) {
                    int tt = g * 32 + j;
                    const float* xr = sX + (buf * 64 + tt) * SXW;
                    float dtv = sdt[tt * 8 + wid];
                    float xcv = __bfloat162float(sxcb[(buf * 64 + tt) * 8 + wid]);
                    float du = dtv * xcv;
                    float dA0 = __expf(dtv * A0);
                    float r32 = __shfl_sync(0xffffffffu, dA0, 31);
                    float dA1 = dA0 * r32;
                    h0 = fmaf(dA0, h0, du * xr[16 + lane]);
                    h1 = fmaf(dA1, h1, du * xr[48 + lane]);
                    part[j] = fmaf(h0, xr[80 + lane], h1 * xr[112 + lane]);
                }
                #pragma unroll
                for (int s = 16; s >= 1; s >>= 1) {
                    bool up = (lane & s) != 0;
                    #pragma unroll
                    for (int i2 = 0; i2 < 16; i2++) {
                        if (i2 >= s) break;
                        float keep = up ? part[i2 + s] : part[i2];
                        float send = up ? part[i2] : part[i2 + s];
                        part[i2] = keep + __shfl_xor_sync(0xffffffffu, send, s);
                    }
                }
                int tt = g * 32 + lane;
                float xcv = __bfloat162float(sxcb[(buf * 64 + tt) * 8 + wid]);
                float zv = __bfloat162float(szb[(buf * 64 + tt) * 8 + wid]);
                float gate = zv / (1.0f + __expf(-zv));
                sy[tt * 8 + wid] = fmaf(xcv, Dd, part[0]) * gate;
            }
        } else {
            #pragma unroll 1
            for (int g = 0; g < TCHUNK / 32; g++) {
                float part[32];
                #pragma unroll
                for (int j = 0; j < 32; j++) {
                    int tt = g * 32 + j;
                    const float* xr = sX + (buf * 64 + tt) * SXW;
                    float dtv = sdt[tt * 8 + wid];
                    float xcv = __bfloat162float(sxcb[(buf * 64 + tt) * 8 + wid]);
                    float du = dtv * xcv;
                    float dA0 = __expf(dtv * A0);
                    float dA1 = __expf(dtv * A1);
                    h0 = fmaf(dA0, h0, du * xr[16 + lane]);
                    h1 = fmaf(dA1, h1, du * xr[48 + lane]);
                    part[j] = fmaf(h0, xr[80 + lane], h1 * xr[112 + lane]);
                }
                #pragma unroll
                for (int s = 16; s >= 1; s >>= 1) {
                    bool up = (lane & s) != 0;
                    #pragma unroll
                    for (int i2 = 0; i2 < 16; i2++) {
                        if (i2 >= s) break;
                        float keep = up ? part[i2 + s] : part[i2];
                        float send = up ? part[i2] : part[i2 + s];
                        part[i2] = keep + __shfl_xor_sync(0xffffffffu, send, s);
                    }
                }
                int tt = g * 32 + lane;
                float xcv = __bfloat162float(sxcb[(buf * 64 + tt) * 8 + wid]);
                float zv = __bfloat162float(szb[(buf * 64 + tt) * 8 + wid]);
                float gate = zv / (1.0f + __expf(-zv));
                sy[tt * 8 + wid] = fmaf(xcv, Dd, part[0]) * gate;
            }
        }
        __syncthreads();
        for (int i = tid; i < TCHUNK * 8; i += 256) {
            int tt = i >> 3, di = i & 7;
            y_bf[(size_t)(b * LSEQ + c * TCHUNK + tt) * DI + dbase + di] =
                __float2bfloat16_rn(sy[tt * 8 + di]);
        }
        __syncthreads();
    }
}

// ---------------------------------------------------------------------------
// Forward packed-real 2048-pt FFT (DIF, natural -> bit-reversed).
// ---------------------------------------------------------------------------
#define FSTR 2049
#define FFTF_SMEM (4 * FSTR * 4)
#define FFTI_SMEM (12 * FSTR * 4)

__global__ void __launch_bounds__(512) fft_fwd_kernel(const __nv_bfloat16* __restrict__ xin,
                                                      __nv_bfloat16* __restrict__ dR,
                                                      __nv_bfloat16* __restrict__ dI) {
    extern __shared__ float sm[];
    float* zr = sm;                // [2][FSTR]
    float* zi = sm + 2 * FSTR;     // [2][FSTR]
    int b = blockIdx.x >> 6;
    int c0 = (blockIdx.x & 63) * 4;
    size_t base = (size_t)b * LSEQ * DIMC + c0;
    int tid = threadIdx.x;

    for (int n = tid; n < 2048; n += 512) {
        const __nv_bfloat162* p = (const __nv_bfloat162*)(xin + base + (size_t)n * DIMC);
        __nv_bfloat162 a = p[0], bb = p[1];
        zr[0 * FSTR + n] = __bfloat162float(a.x);
        zi[0 * FSTR + n] = __bfloat162float(a.y);
        zr[1 * FSTR + n] = __bfloat162float(bb.x);
        zi[1 * FSTR + n] = __bfloat162float(bb.y);
    }
    __syncthreads();

    #pragma unroll
    for (int hb = 10; hb >= 0; hb--) {
        int half = 1 << hb;
        float th = -PI_F / (float)half;
        for (int e = tid; e < 2048; e += 512) {
            int col = e >> 10, idx = e & 1023;
            int j = idx & (half - 1);
            int pos = ((idx >> hb) << (hb + 1)) + j;
            float* cr = zr + col * FSTR;
            float* ci = zi + col * FSTR;
            float ar = cr[pos],        ai = ci[pos];
            float br = cr[pos + half], bi = ci[pos + half];
            float wi, wr;
            __sincosf(th * (float)j, &wi, &wr);
            float xr = ar - br, xi = ai - bi;
            cr[pos] = ar + br;  ci[pos] = ai + bi;
            cr[pos + half] = xr * wr - xi * wi;
            ci[pos + half] = xr * wi + xi * wr;
        }
        __syncthreads();
    }

    for (int e = tid; e < 4096; e += 512) {
        int col = e >> 11, p = e & 2047;
        int k = rev11(p);
        int pp = rev11((2048 - k) & 2047);
        float ar = zr[col * FSTR + p],  ai = zi[col * FSTR + p];
        float br = zr[col * FSTR + pp], bi = zi[col * FSTR + pp];
        float f0r = 0.5f * (ar + br), f0i = 0.5f * (ai - bi);
        float f1r = 0.5f * (ai + bi), f1i = 0.5f * (br - ar);
        __nv_bfloat162* pr = (__nv_bfloat162*)(dR + base + (size_t)p * DIMC + 2 * col);
        __nv_bfloat162* pi = (__nv_bfloat162*)(dI + base + (size_t)p * DIMC + 2 * col);
        *pr = __nv_bfloat162(__float2bfloat16_rn(f0r), __float2bfloat16_rn(f1r));
        *pi = __nv_bfloat162(__float2bfloat16_rn(f0i), __float2bfloat16_rn(f1i));
    }
}

// ---------------------------------------------------------------------------
// Inverse packed-real 2048-pt FFT; Re->even ch, Im->odd ch; + fp32 residual.
// ---------------------------------------------------------------------------
__global__ void __launch_bounds__(512) fft_inv_kernel(const __nv_bfloat16* __restrict__ dR,
                                                      const __nv_bfloat16* __restrict__ dI,
                                                      const float* __restrict__ x1,
                                                      float* __restrict__ out) {
    extern __shared__ float sm[];
    float* fr = sm;                 // [4][FSTR]
    float* fi = sm + 4 * FSTR;      // [4][FSTR]
    float* zr = sm + 8 * FSTR;      // [2][FSTR]
    float* zi = sm + 10 * FSTR;     // [2][FSTR]
    int b = blockIdx.x >> 6;
    int c0 = (blockIdx.x & 63) * 4;
    size_t base = (size_t)b * LSEQ * DIMC + c0;
    int tid = threadIdx.x;

    for (int n = tid; n < 2048; n += 512) {
        const __nv_bfloat162* pr = (const __nv_bfloat162*)(dR + base + (size_t)n * DIMC);
        const __nv_bfloat162* pi = (const __nv_bfloat162*)(dI + base + (size_t)n * DIMC);
        __nv_bfloat162 r0 = pr[0], r1 = pr[1], i0 = pi[0], i1 = pi[1];
        fr[0 * FSTR + n] = __bfloat162float(r0.x);
        fr[1 * FSTR + n] = __bfloat162float(r0.y);
        fr[2 * FSTR + n] = __bfloat162float(r1.x);
        fr[3 * FSTR + n] = __bfloat162float(r1.y);
        fi[0 * FSTR + n] = __bfloat162float(i0.x);
        fi[1 * FSTR + n] = __bfloat162float(i0.y);
        fi[2 * FSTR + n] = __bfloat162float(i1.x);
        fi[3 * FSTR + n] = __bfloat162float(i1.y);
    }
    __syncthreads();

    for (int e = tid; e < 4096; e += 512) {
        int col = e >> 11, p = e & 2047;
        int pp = rev11((2048 - rev11(p)) & 2047);
        int ca = 2 * col, cb = 2 * col + 1;
        float Zr = 0.5f * (fr[ca * FSTR + p] + fr[ca * FSTR + pp])
                 - 0.5f * (fi[cb * FSTR + p] - fi[cb * FSTR + pp]);
        float Zi = 0.5f * (fi[ca * FSTR + p] - fi[ca * FSTR + pp])
                 + 0.5f * (fr[cb * FSTR + p] + fr[cb * FSTR + pp]);
        zr[col * FSTR + p] = Zr;
        zi[col * FSTR + p] = Zi;
    }
    __syncthreads();

    #pragma unroll
    for (int hb = 0; hb <= 10; hb++) {
        int half = 1 << hb;
        float th = PI_F / (float)half;
        for (int e = tid; e < 2048; e += 512) {
            int col = e >> 10, idx = e & 1023;
            int j = idx & (half - 1);
            int pos = ((idx >> hb) << (hb + 1)) + j;
            float* cr = zr + col * FSTR;
            float* ci = zi + col * FSTR;
            float ar = cr[pos],        ai = ci[pos];
            float br = cr[pos + half], bi = ci[pos + half];
            float wi, wr;
            __sincosf(th * (float)j, &wi, &wr);
            float tr = br * wr - bi * wi;
            float ti = br * wi + bi * wr;
            cr[pos] = ar + tr;         ci[pos] = ai + ti;
            cr[pos + half] = ar - tr;  ci[pos + half] = ai - ti;
        }
        __syncthreads();
    }

    for (int n = tid; n < 2048; n += 512) {
        size_t a = base + (size_t)n * DIMC;
        float4 rx = *(const float4*)(x1 + a);
        float4 o;
        o.x = rx.x + zr[0 * FSTR + n];
        o.y = rx.y + zi[0 * FSTR + n];
        o.z = rx.z + zr[1 * FSTR + n];
        o.w = rx.w + zi[1 * FSTR + n];
        *(float4*)(out + a) = o;
    }
}

// ---------------------------------------------------------------------------
// EinFFT MLP with DFT4/IDFT4 folded in; bf16 global I/O, f32x2 packed FMA.
// ---------------------------------------------------------------------------
__global__ void __launch_bounds__(256) einfft_mlp_kernel(
        __nv_bfloat16* __restrict__ fR, __nv_bfloat16* __restrict__ fI,
        const float* __restrict__ cw1, const float* __restrict__ cb1,
        const float* __restrict__ cw2, const float* __restrict__ cb2) {
    __shared__ __align__(16) float sR[2048], sI[2048];
    __shared__ __align__(16) float tR[2048], tI[2048];
    int row0 = blockIdx.x * 8;
    int tid = threadIdx.x;
    {
        const __nv_bfloat162* fr2 = (const __nv_bfloat162*)(fR + (size_t)row0 * DIMC);
        const __nv_bfloat162* fi2 = (const __nv_bfloat162*)(fI + (size_t)row0 * DIMC);
        for (int i = tid; i < 1024; i += 256) {
            __nv_bfloat162 r = fr2[i], m = fi2[i];
            sR[2*i] = __bfloat162float(r.x); sR[2*i+1] = __bfloat162float(r.y);
            sI[2*i] = __bfloat162float(m.x); sI[2*i+1] = __bfloat162float(m.y);
        }
    }
    __syncthreads();

    const float sc = SQRT_INV_8192;
    #pragma unroll
    for (int g = tid; g < 512; g += 256) {
        int r = g >> 6, s = g & 63;
        int p = r * 256 + s;
        float r0 = sR[p],       i0 = sI[p];
        float r1 = sR[p + 64],  i1 = sI[p + 64];
        float r2 = sR[p + 128], i2 = sI[p + 128];
        float r3 = sR[p + 192], i3 = sI[p + 192];
        sR[p]       = (r0 + r1 + r2 + r3) * sc;
        sI[p]       = (i0 + i1 + i2 + i3) * sc;
        sR[p + 64]  = (r0 + i1 - r2 - i3) * sc;
        sI[p + 64]  = (i0 - r1 - i2 + r3) * sc;
        sR[p + 128] = (r0 - r1 + r2 - r3) * sc;
        sI[p + 128] = (i0 - i1 + i2 - i3) * sc;
        sR[p + 192] = (r0 - i1 - r2 + i3) * sc;
        sI[p + 192] = (i0 + r1 - i2 - r3) * sc;
    }
    __syncthreads();

    int k = tid >> 6, o = tid & 63;

    {
        const float* w0 = cw1 + k * 4096;
        const float* w1 = cw1 + 16384 + k * 4096;
        float bR = cb1[k * 64 + o];
        float bI = cb1[256 + k * 64 + o];
        u64 aRp[8], aIp[8];
        #pragma unroll
        for (int r = 0; r < 8; r++) {
            aRp[r] = packf2(bR, 0.0f);
            aIp[r] = packf2(bI, 0.0f);
        }
        #pragma unroll 4
        for (int dd = 0; dd < 64; dd += 2) {
            float wa0 = w0[dd * 64 + o], wa1 = w0[(dd + 1) * 64 + o];
            float wb0 = w1[dd * 64 + o], wb1 = w1[(dd + 1) * 64 + o];
            u64 wa_p  = packf2(wa0, wa1);
            u64 wb_p  = packf2(wb0, wb1);
            u64 wbn_p = packf2(-wb0, -wb1);
            int sb = k * 64 + dd;
            #pragma unroll
            for (int r = 0; r < 8; r++) {
                float2 xr2 = *(const float2*)&sR[r * 256 + sb];
                float2 xi2 = *(const float2*)&sI[r * 256 + sb];
                u64 xr_p = packf2(xr2.x, xr2.y);
                u64 xi_p = packf2(xi2.x, xi2.y);
                fma2(aRp[r], xr_p, wa_p, aRp[r]);
                fma2(aRp[r], xi_p, wbn_p, aRp[r]);
                fma2(aIp[r], xr_p, wb_p, aIp[r]);
                fma2(aIp[r], xi_p, wa_p, aIp[r]);
            }
        }
        #pragma unroll
        for (int r = 0; r < 8; r++) {
            float lo, hi;
            unpackf2(aRp[r], lo, hi);
            tR[r * 256 + tid] = fmaxf(lo + hi, 0.0f);
            unpackf2(aIp[r], lo, hi);
            tI[r * 256 + tid] = fmaxf(lo + hi, 0.0f);
        }
    }
    __syncthreads();

    {
        const float* w0 = cw2 + k * 4096;
        const float* w1 = cw2 + 16384 + k * 4096;
        float bR = cb2[k * 64 + o];
        float bI = cb2[256 + k * 64 + o];
        u64 aRp[8], aIp[8];
        #pragma unroll
        for (int r = 0; r < 8; r++) {
            aRp[r] = packf2(bR, 0.0f);
            aIp[r] = packf2(bI, 0.0f);
        }
        #pragma unroll 4
        for (int dd = 0; dd < 64; dd += 2) {
            float wa0 = w0[dd * 64 + o], wa1 = w0[(dd + 1) * 64 + o];
            float wb0 = w1[dd * 64 + o], wb1 = w1[(dd + 1) * 64 + o];
            u64 wa_p  = packf2(wa0, wa1);
            u64 wb_p  = packf2(wb0, wb1);
            u64 wbn_p = packf2(-wb0, -wb1);
            int sb = k * 64 + dd;
            #pragma unroll
            for (int r = 0; r < 8; r++) {
                float2 xr2 = *(const float2*)&tR[r * 256 + sb];
                float2 xi2 = *(const float2*)&tI[r * 256 + sb];
                u64 xr_p = packf2(xr2.x, xr2.y);
                u64 xi_p = packf2(xi2.x, xi2.y);
                fma2(aRp[r], xr_p, wa_p, aRp[r]);
                fma2(aRp[r], xi_p, wbn_p, aRp[r]);
                fma2(aIp[r], xr_p, wb_p, aIp[r]);
                fma2(aIp[r], xi_p, wa_p, aIp[r]);
            }
        }
        #pragma unroll
        for (int r = 0; r < 8; r++) {
            float lo, hi;
            unpackf2(aRp[r], lo, hi);
            float vR = lo + hi;
            unpackf2(aIp[r], lo, hi);
            float vI = lo + hi;
            vR = (vR > LAMBDA_SS) ? vR - LAMBDA_SS
                 : ((vR < -LAMBDA_SS) ? vR + LAMBDA_SS : 0.0f);
            vI = (vI > LAMBDA_SS) ? vI - LAMBDA_SS
                 : ((vI < -LAMBDA_SS) ? vI + LAMBDA_SS : 0.0f);
            sR[r * 256 + tid] = vR;
            sI[r * 256 + tid] = vI;
        }
    }
    __syncthreads();

    #pragma unroll
    for (int g = tid; g < 512; g += 256) {
        int r = g >> 6, s = g & 63;
        int p = r * 256 + s;
        float R0 = sR[p],       I0 = sI[p];
        float R1 = sR[p + 64],  I1 = sI[p + 64];
        float R2 = sR[p + 128], I2 = sI[p + 128];
        float R3 = sR[p + 192], I3 = sI[p + 192];
        sR[p]       = (R0 + R1 + R2 + R3) * sc;
        sI[p]       = (I0 + I1 + I2 + I3) * sc;
        sR[p + 64]  = (R0 - I1 - R2 + I3) * sc;
        sI[p + 64]  = (I0 + R1 - I2 - R3) * sc;
        sR[p + 128] = (R0 - R1 + R2 - R3) * sc;
        sI[p + 128] = (I0 - I1 + I2 - I3) * sc;
        sR[p + 192] = (R0 + I1 - R2 - I3) * sc;
        sI[p + 192] = (I0 - R1 - I2 + R3) * sc;
    }
    __syncthreads();

    {
        __nv_bfloat162* fr2 = (__nv_bfloat162*)(fR + (size_t)row0 * DIMC);
        __nv_bfloat162* fi2 = (__nv_bfloat162*)(fI + (size_t)row0 * DIMC);
        for (int i = tid; i < 1024; i += 256) {
            fr2[i] = __nv_bfloat162(__float2bfloat16_rn(sR[2*i]),
                                    __float2bfloat16_rn(sR[2*i+1]));
            fi2[i] = __nv_bfloat162(__float2bfloat16_rn(sI[2*i]),
                                    __float2bfloat16_rn(sI[2*i+1]));
        }
    }
}

// ---------------------------------------------------------------------------
// Launch
// ---------------------------------------------------------------------------
extern "C" void kernel_launch(void* const* d_in, const int* in_sizes, int n_in,
                              void* d_out, int out_size) {
    const float* x         = (const float*)d_in[0];
    const float* norm1_w   = (const float*)d_in[1];
    const float* norm1_b   = (const float*)d_in[2];
    const float* in_proj_w = (const float*)d_in[3];
    const float* conv_w    = (const float*)d_in[4];
    const float* conv_b    = (const float*)d_in[5];
    const float* x_proj_w  = (const float*)d_in[6];
    const float* dt_proj_w = (const float*)d_in[7];
    const float* dt_proj_b = (const float*)d_in[8];
    const float* A_log     = (const float*)d_in[9];
    const float* Dvec      = (const float*)d_in[10];
    const float* out_proj_w= (const float*)d_in[11];
    const float* norm2_w   = (const float*)d_in[12];
    const float* norm2_b   = (const float*)d_in[13];
    const float* cw1       = (const float*)d_in[14];
    const float* cb1       = (const float*)d_in[15];
    const float* cw2       = (const float*)d_in[16];
    const float* cb2       = (const float*)d_in[17];
    float* out = (float*)d_out;

    void* sp = nullptr;
    cudaGetSymbolAddress(&sp, SCRATCH);
    float* S = (float*)sp;
    float* s_xdbl = S + O_XDBL;
    float* s_x1   = S + O_X1;
    __nv_bfloat16* s_xzb  = (__nv_bfloat16*)(S + O_XZB);
    __nv_bfloat16* s_xnbf = (__nv_bfloat16*)(S + O_XNBF);
    __nv_bfloat16* s_xcbf = (__nv_bfloat16*)(S + O_XCBF);
    __nv_bfloat16* s_ybf  = (__nv_bfloat16*)(S + O_YBF);
    __nv_bfloat16* s_xn2b = (__nv_bfloat16*)(S + O_XN2B);
    __nv_bfloat16* s_frb  = (__nv_bfloat16*)(S + O_FRB);
    __nv_bfloat16* s_fib  = (__nv_bfloat16*)(S + O_FIB);
    __nv_bfloat16* s_wbf  = (__nv_bfloat16*)(S + O_WBF);
    __nv_bfloat16* win_bf = s_wbf;
    __nv_bfloat16* wx_bf  = s_wbf + W_IN_SZ;
    __nv_bfloat16* wo_bf  = s_wbf + W_IN_SZ + W_X_SZ;

    static int attr_done = 0;
    if (!attr_done) {
        cudaFuncSetAttribute(fft_fwd_kernel,
                             cudaFuncAttributeMaxDynamicSharedMemorySize, FFTF_SMEM);
        cudaFuncSetAttribute(fft_inv_kernel,
                             cudaFuncAttributeMaxDynamicSharedMemorySize, FFTI_SMEM);
        cudaFuncSetAttribute(gemm_bf16,
                             cudaFuncAttributeMaxDynamicSharedMemorySize, GEMM_SMEM);
        cudaFuncSetAttribute(scan_kernel,
                             cudaFuncAttributeMaxDynamicSharedMemorySize, SCAN_SMEM);
        attr_done = 1;
    }

    // 0) prep: weight convert + LN1 (merged)
    prep_kernel<<<WCVT_BLOCKS + NTOK / 8, 256>>>(in_proj_w, x_proj_w, out_proj_w,
                                                 s_wbf, x, norm1_w, norm1_b, s_xnbf);
    // 1) in_proj -> bf16 xz
    gemm_bf16<<<dim3((2 * DI) / GBN, NTOK / GBM), 256, GEMM_SMEM>>>(
        s_xnbf, win_bf, nullptr, nullptr, s_xzb, NTOK, 2 * DI, DIMC);
    // 2) conv + silu -> bf16 xc
    conv_silu_kernel<<<(NTOK * DI) / 256, 256>>>(s_xzb, conv_w, conv_b, s_xcbf);
    // 3) x_proj -> fp32 xdbl
    gemm_bf16<<<dim3((XDBLW + GBN - 1) / GBN, NTOK / GBM), 256, GEMM_SMEM>>>(
        s_xcbf, wx_bf, nullptr, s_xdbl, nullptr, NTOK, XDBLW, DI);
    // 4) selective scan -> bf16 y (halved MUFU via exp-additivity)
    scan_kernel<<<BATCH * (DI / 8), 256, SCAN_SMEM>>>(
        s_xdbl, s_xcbf, s_xzb, A_log, Dvec, dt_proj_w, dt_proj_b, s_ybf);
    // 5) out_proj + residual -> fp32 x1
    gemm_bf16<<<dim3(DIMC / GBN, NTOK / GBM), 256, GEMM_SMEM>>>(
        s_ybf, wo_bf, x, s_x1, nullptr, NTOK, DIMC, DI);
    // 6) LN2 -> bf16
    ln_kernel<<<NTOK / 8, 256>>>(s_x1, norm2_w, norm2_b, nullptr, s_xn2b);
    // 7) forward packed-real FFT
    fft_fwd_kernel<<<128, 512, FFTF_SMEM>>>(s_xn2b, s_frb, s_fib);
    // 8) fused EinFFT MLP
    einfft_mlp_kernel<<<NTOK / 8, 256>>>(s_frb, s_fib, cw1, cb1, cw2, cb2);
    // 9) inverse packed-real FFT + residual -> out
    fft_inv_kernel<<<128, 512, FFTI_SMEM>>>(s_frb, s_fib, s_x1, out);
}